// round 1
// baseline (speedup 1.0000x reference)
#include <cuda_runtime.h>
#include <cstdint>

// ---------------------------------------------------------------------------
// LargeLoss: loss = pos_mask*bce(x,t) + neg_mask*[unobs < kth_largest(unobs)]*bce(-x,-t)
//   unobs = neg_mask * bce(-x,-t)  (>= 0)
// Strategy:
//   Encode per element into scratch g_enc:
//     t > 0 : -(pos_loss)   (sign bit set -> not a top-k candidate, value = pos_loss)
//     t < 0 : +(neg_loss)   (candidate, value participates in top-k)
//     t == 0: -0.0f         (not a candidate, output 0)
//   Exact k-th largest of {candidate values, zeros elsewhere} via 3-stage
//   radix select on the fp32 bit pattern (12 / 12 / 8 bits), since for
//   non-negative floats uint ordering == float ordering.
//   Finalize: sign bit set -> |enc| ; else enc * (enc < thr).
// All selection state in __device__ globals; 8 kernel launches; graph-safe.
// ---------------------------------------------------------------------------

#define N_ELEMS (2048 * 5000)

__device__ float    g_enc[N_ELEMS];
__device__ unsigned g_hist1[4096];
__device__ unsigned g_hist2[4096];
__device__ unsigned g_hist3[256];
__device__ unsigned g_k0, g_k1, g_k2, g_k3;
__device__ unsigned g_p1, g_p2, g_p3;

// ---------------------------------------------------------------------------
__global__ void init_kernel(const int* __restrict__ kin) {
    int t = blockIdx.x * blockDim.x + threadIdx.x;
    int stride = gridDim.x * blockDim.x;
    for (int i = t; i < 4096; i += stride) { g_hist1[i] = 0u; g_hist2[i] = 0u; }
    if (t < 256) g_hist3[t] = 0u;
    if (t == 0) {
        int k = *kin;
        g_k0 = (k > 0) ? (unsigned)k : 0u;
    }
}

// ---------------------------------------------------------------------------
__device__ __forceinline__ float encode_one(float x, float t) {
    float ax  = fabsf(x);
    float lse = log1pf(expf(-ax));           // log(1 + e^-|x|)
    if (t > 0.0f)  return -(fmaxf(-x, 0.0f) + lse);  // -(pos_loss), pos_loss > 0
    if (t < 0.0f)  return  (fmaxf( x, 0.0f) + lse);  //  neg_loss  >= 0
    return -0.0f;                                     // unobserved
}

// Pass 1: encode + 12-bit (bits 31:20) histogram with shared privatization.
__global__ void encode_hist1_kernel(const float* __restrict__ in,
                                    const float* __restrict__ tg,
                                    int n) {
    __shared__ unsigned h[4096];
    for (int i = threadIdx.x; i < 4096; i += blockDim.x) h[i] = 0u;
    __syncthreads();

    const int n4 = n >> 2;
    const float4* in4 = (const float4*)in;
    const float4* tg4 = (const float4*)tg;
    float4* e4 = (float4*)g_enc;

    unsigned zc = 0;  // per-thread aggregated count of non-candidates (bin 0)
    int stride = gridDim.x * blockDim.x;
    for (int i = blockIdx.x * blockDim.x + threadIdx.x; i < n4; i += stride) {
        float4 x = in4[i];
        float4 t = tg4[i];
        float4 e;
        e.x = encode_one(x.x, t.x);
        e.y = encode_one(x.y, t.y);
        e.z = encode_one(x.z, t.z);
        e.w = encode_one(x.w, t.w);
        e4[i] = e;
        float lanes[4] = {e.x, e.y, e.z, e.w};
#pragma unroll
        for (int l = 0; l < 4; ++l) {
            unsigned u   = __float_as_uint(lanes[l]);
            unsigned sel = (u >> 31) ? 0u : u;
            if (sel) atomicAdd(&h[sel >> 20], 1u);
            else     zc++;
        }
    }
    // scalar tail (n not multiple of 4)
    if (blockIdx.x == 0) {
        for (int i = (n4 << 2) + threadIdx.x; i < n; i += blockDim.x) {
            float e = encode_one(in[i], tg[i]);
            g_enc[i] = e;
            unsigned u   = __float_as_uint(e);
            unsigned sel = (u >> 31) ? 0u : u;
            if (sel) atomicAdd(&h[sel >> 20], 1u);
            else     zc++;
        }
    }
    if (zc) atomicAdd(&h[0], zc);
    __syncthreads();
    for (int i = threadIdx.x; i < 4096; i += blockDim.x)
        if (h[i]) atomicAdd(&g_hist1[i], h[i]);
}

// Pass 2: refine within the selected 12-bit bucket on bits 19:8.
__global__ void hist2_kernel(int n) {
    __shared__ unsigned h[4096];
    for (int i = threadIdx.x; i < 4096; i += blockDim.x) h[i] = 0u;
    __syncthreads();

    const unsigned p1 = g_p1;
    const int n4 = n >> 2;
    const uint4* e4 = (const uint4*)g_enc;
    int stride = gridDim.x * blockDim.x;
    for (int i = blockIdx.x * blockDim.x + threadIdx.x; i < n4; i += stride) {
        uint4 u = e4[i];
        unsigned lanes[4] = {u.x, u.y, u.z, u.w};
#pragma unroll
        for (int l = 0; l < 4; ++l) {
            unsigned sel = (lanes[l] >> 31) ? 0u : lanes[l];
            if ((sel >> 20) == p1) atomicAdd(&h[(sel >> 8) & 0xFFFu], 1u);
        }
    }
    if (blockIdx.x == 0) {
        const unsigned* e = (const unsigned*)g_enc;
        for (int i = (n4 << 2) + threadIdx.x; i < n; i += blockDim.x) {
            unsigned u = e[i];
            unsigned sel = (u >> 31) ? 0u : u;
            if ((sel >> 20) == p1) atomicAdd(&h[(sel >> 8) & 0xFFFu], 1u);
        }
    }
    __syncthreads();
    for (int i = threadIdx.x; i < 4096; i += blockDim.x)
        if (h[i]) atomicAdd(&g_hist2[i], h[i]);
}

// Pass 3: refine within the 24-bit prefix on bits 7:0.
__global__ void hist3_kernel(int n) {
    __shared__ unsigned h[256];
    for (int i = threadIdx.x; i < 256; i += blockDim.x) h[i] = 0u;
    __syncthreads();

    const unsigned p2 = g_p2;
    const int n4 = n >> 2;
    const uint4* e4 = (const uint4*)g_enc;
    int stride = gridDim.x * blockDim.x;
    for (int i = blockIdx.x * blockDim.x + threadIdx.x; i < n4; i += stride) {
        uint4 u = e4[i];
        unsigned lanes[4] = {u.x, u.y, u.z, u.w};
#pragma unroll
        for (int l = 0; l < 4; ++l) {
            unsigned sel = (lanes[l] >> 31) ? 0u : lanes[l];
            if ((sel >> 8) == p2) atomicAdd(&h[sel & 0xFFu], 1u);
        }
    }
    if (blockIdx.x == 0) {
        const unsigned* e = (const unsigned*)g_enc;
        for (int i = (n4 << 2) + threadIdx.x; i < n; i += blockDim.x) {
            unsigned u = e[i];
            unsigned sel = (u >> 31) ? 0u : u;
            if ((sel >> 8) == p2) atomicAdd(&h[sel & 0xFFu], 1u);
        }
    }
    __syncthreads();
    for (int i = threadIdx.x; i < 256; i += blockDim.x)
        if (h[i]) atomicAdd(&g_hist3[i], h[i]);
}

// ---------------------------------------------------------------------------
// Single-block: suffix-sum the histogram, pick the bin containing rank k
// (from the top), emit refined prefix and residual rank. stage: 0,1,2.
__global__ void select_kernel(int stage) {
    __shared__ unsigned sh[4096];
    const unsigned* hist = (stage == 0) ? g_hist1 : (stage == 1) ? g_hist2 : g_hist3;
    const int nbins      = (stage == 2) ? 256 : 4096;
    const unsigned k     = (stage == 0) ? g_k0 : (stage == 1) ? g_k1 : g_k2;
    const unsigned pin   = (stage == 0) ? 0u   : (stage == 1) ? g_p1 : g_p2;
    const int shift      = (stage == 2) ? 8 : 12;

    int t = threadIdx.x;
    for (int i = t; i < nbins; i += blockDim.x) sh[i] = hist[i];
    __syncthreads();

    // Hillis-Steele suffix sums: sh[i] = sum_{j>=i} hist[j]
    for (int off = 1; off < nbins; off <<= 1) {
        unsigned add[4];
        int c = 0;
        for (int i = t; i < nbins; i += blockDim.x)
            add[c++] = (i + off < nbins) ? sh[i + off] : 0u;
        __syncthreads();
        c = 0;
        for (int i = t; i < nbins; i += blockDim.x) sh[i] += add[c++];
        __syncthreads();
    }

    if (k == 0u) {  // k==0: no masking; finalize handles via +inf threshold
        if (t == 0) {
            if (stage == 0)      { g_p1 = 0u; g_k1 = 0u; }
            else if (stage == 1) { g_p2 = 0u; g_k2 = 0u; }
            else                 { g_p3 = 0u; g_k3 = 0u; }
        }
        return;
    }
    // unique bin b with suffix[b] >= k and suffix[b+1] < k
    for (int i = t; i < nbins; i += blockDim.x) {
        unsigned s  = sh[i];
        unsigned sn = (i + 1 < nbins) ? sh[i + 1] : 0u;
        if (s >= k && sn < k) {
            unsigned p  = (pin << shift) | (unsigned)i;
            unsigned kr = k - sn;
            if (stage == 0)      { g_p1 = p; g_k1 = kr; }
            else if (stage == 1) { g_p2 = p; g_k2 = kr; }
            else                 { g_p3 = p; g_k3 = kr; }
        }
    }
}

// ---------------------------------------------------------------------------
__global__ void finalize_kernel(float* __restrict__ out, int n) {
    const float thr = (g_k0 == 0u) ? __int_as_float(0x7f800000)  // +inf
                                   : __uint_as_float(g_p3);
    const int n4 = n >> 2;
    const float4* e4 = (const float4*)g_enc;
    float4* o4 = (float4*)out;
    int stride = gridDim.x * blockDim.x;
    for (int i = blockIdx.x * blockDim.x + threadIdx.x; i < n4; i += stride) {
        float4 e = e4[i];
        float4 o;
        float le[4] = {e.x, e.y, e.z, e.w};
        float lo[4];
#pragma unroll
        for (int l = 0; l < 4; ++l) {
            unsigned u = __float_as_uint(le[l]);
            if (u >> 31) lo[l] = __uint_as_float(u & 0x7FFFFFFFu);   // pos_loss or 0
            else         lo[l] = (le[l] < thr) ? le[l] : 0.0f;       // masked neg_loss
        }
        o.x = lo[0]; o.y = lo[1]; o.z = lo[2]; o.w = lo[3];
        o4[i] = o;
    }
    if (blockIdx.x == 0) {
        for (int i = (n4 << 2) + threadIdx.x; i < n; i += blockDim.x) {
            unsigned u = __float_as_uint(g_enc[i]);
            float v;
            if (u >> 31) v = __uint_as_float(u & 0x7FFFFFFFu);
            else { float e = __uint_as_float(u); v = (e < thr) ? e : 0.0f; }
            out[i] = v;
        }
    }
}

// ---------------------------------------------------------------------------
extern "C" void kernel_launch(void* const* d_in, const int* in_sizes, int n_in,
                              void* d_out, int out_size) {
    const float* inp  = (const float*)d_in[0];
    const float* tgt  = (const float*)d_in[1];
    const int*   kptr = (const int*)d_in[2];
    float* out = (float*)d_out;
    const int n = in_sizes[0];

    const int BLOCK = 256;
    const int GRID  = 1184;  // 148 SMs * 8

    init_kernel<<<8, 1024>>>(kptr);
    encode_hist1_kernel<<<GRID, BLOCK>>>(inp, tgt, n);
    select_kernel<<<1, 1024>>>(0);
    hist2_kernel<<<GRID, BLOCK>>>(n);
    select_kernel<<<1, 1024>>>(1);
    hist3_kernel<<<GRID, BLOCK>>>(n);
    select_kernel<<<1, 1024>>>(2);
    finalize_kernel<<<GRID, BLOCK>>>(out, n);
}

// round 2
// speedup vs baseline: 1.1940x; 1.1940x over previous
#include <cuda_runtime.h>
#include <cstdint>

// ---------------------------------------------------------------------------
// LargeLoss via radix-select on RAW INPUT BITS.
//   neg_loss = softplus(x) is monotone in x, candidates (t<0) always > 0,
//   so kth-largest unobserved loss == softplus(kth-largest x among t<0).
// Pipeline:
//   init     : zero hist1, counter, load k
//   passA    : stream in+tg, 12-bit histogram of candidate keys + compact
//              all candidate keys (sign-flipped float bits) into g_keys
//   select 0 : pick 12-bit bucket, residual rank, mode flags; zero hist2
//   passB    : scan compacted keys, 12-bit refinement (bits 19:8); zero'd hist
//   select 1 : pick 24-bit prefix; zero hist3
//   passC    : scan compacted keys, 8-bit refinement (bits 7:0)
//   select 2 : exact kth key -> threshold loss = softplus(decode(key))
//   finalize : stream in+tg, compute losses, mask negatives by (loss < thr)
// ---------------------------------------------------------------------------

#define N_MAX 10240000

__device__ unsigned g_keys[N_MAX];
__device__ unsigned g_hist1[4096];
__device__ unsigned g_hist2[4096];
__device__ unsigned g_hist3[256];
__device__ unsigned g_cnt;
__device__ unsigned g_k0, g_k1, g_k2;
__device__ unsigned g_p1, g_p2;
__device__ int      g_mode;   // 0 = normal, 1 = keep all (k==0), 2 = drop all (k > #cand)
__device__ float    g_thr;

// ---------------------------------------------------------------------------
__device__ __forceinline__ unsigned f2key(float x) {
    unsigned b = __float_as_uint(x);
    return (b & 0x80000000u) ? ~b : (b | 0x80000000u);
}
__device__ __forceinline__ float key2f(unsigned k) {
    unsigned b = (k & 0x80000000u) ? (k & 0x7FFFFFFFu) : ~k;
    return __uint_as_float(b);
}
// negative-branch BCE loss:  max(x,0) + log1p(exp(-|x|))   == softplus(x)
__device__ __forceinline__ float neg_loss_f(float x) {
    return fmaxf(x, 0.0f) + log1pf(expf(-fabsf(x)));
}

// ---------------------------------------------------------------------------
__global__ void init_kernel(const int* __restrict__ kin) {
    int t = threadIdx.x;
    for (int i = t; i < 4096; i += blockDim.x) g_hist1[i] = 0u;
    if (t == 0) {
        g_cnt = 0u;
        int k = *kin;
        g_k0 = (k > 0) ? (unsigned)k : 0u;
    }
}

// ---------------------------------------------------------------------------
// Pass A: histogram (bits 31:20 of key) + compaction of candidate keys.
__global__ void passA_kernel(const float* __restrict__ in,
                             const float* __restrict__ tg, int n) {
    __shared__ unsigned hist[4096];
    __shared__ unsigned stage[4096];
    __shared__ unsigned s_cnt, s_base;

    const int tid = threadIdx.x, bs = blockDim.x;
    const int lane = tid & 31;
    for (int i = tid; i < 4096; i += bs) hist[i] = 0u;
    if (tid == 0) s_cnt = 0u;
    __syncthreads();

    const float4* in4 = (const float4*)in;
    const float4* tg4 = (const float4*)tg;
    const int n4 = n >> 2;
    const int step = gridDim.x * bs * 2;

    for (int base = blockIdx.x * bs * 2; base < n4; base += step) {
        int i0 = base + tid;
        int i1 = base + bs + tid;
        bool v0 = i0 < n4, v1 = i1 < n4;
        float4 x0, t0, x1, t1;
        if (v0) { x0 = in4[i0]; t0 = tg4[i0]; }
        if (v1) { x1 = in4[i1]; t1 = tg4[i1]; }

        int c0 = v0 ? ((t0.x < 0.f) + (t0.y < 0.f) + (t0.z < 0.f) + (t0.w < 0.f)) : 0;
        int c1 = v1 ? ((t1.x < 0.f) + (t1.y < 0.f) + (t1.z < 0.f) + (t1.w < 0.f)) : 0;
        unsigned cnt = (unsigned)(c0 + c1);

        // warp inclusive prefix over cnt
        unsigned inc = cnt;
#pragma unroll
        for (int d = 1; d < 32; d <<= 1) {
            unsigned u = __shfl_up_sync(0xffffffffu, inc, d);
            if (lane >= d) inc += u;
        }
        unsigned wtot = __shfl_sync(0xffffffffu, inc, 31);
        unsigned wbase = 0;
        if (lane == 0 && wtot) wbase = atomicAdd(&s_cnt, wtot);
        wbase = __shfl_sync(0xffffffffu, wbase, 0);
        unsigned p = wbase + (inc - cnt);

#define PUSH(xv, tv) do { if ((tv) < 0.f) {                       \
            unsigned kk = f2key(xv);                              \
            atomicAdd(&hist[kk >> 20], 1u);                       \
            stage[p++] = kk; } } while (0)
        if (v0) { PUSH(x0.x, t0.x); PUSH(x0.y, t0.y); PUSH(x0.z, t0.z); PUSH(x0.w, t0.w); }
        if (v1) { PUSH(x1.x, t1.x); PUSH(x1.y, t1.y); PUSH(x1.z, t1.z); PUSH(x1.w, t1.w); }
#undef PUSH

        __syncthreads();
        unsigned c = s_cnt;
        if (c >= 2048u) {
            if (tid == 0) s_base = atomicAdd(&g_cnt, c);
            __syncthreads();
            unsigned gb = s_base;
            for (unsigned j = tid; j < c; j += bs) g_keys[gb + j] = stage[j];
            __syncthreads();
            if (tid == 0) s_cnt = 0u;
            __syncthreads();
        }
    }

    // scalar tail (n % 4), block 0 only — uniform loop for warp ops
    if (blockIdx.x == 0) {
        for (int base = (n >> 2) << 2; base < n; base += bs) {
            int i = base + tid;
            unsigned cnt = 0; unsigned kk = 0;
            if (i < n && tg[i] < 0.f) { kk = f2key(in[i]); cnt = 1; atomicAdd(&hist[kk >> 20], 1u); }
            unsigned inc = cnt;
#pragma unroll
            for (int d = 1; d < 32; d <<= 1) {
                unsigned u = __shfl_up_sync(0xffffffffu, inc, d);
                if (lane >= d) inc += u;
            }
            unsigned wtot = __shfl_sync(0xffffffffu, inc, 31);
            unsigned wbase = 0;
            if (lane == 0 && wtot) wbase = atomicAdd(&s_cnt, wtot);
            wbase = __shfl_sync(0xffffffffu, wbase, 0);
            if (cnt) stage[wbase + inc - 1] = kk;
        }
    }

    // final flush
    __syncthreads();
    unsigned c = s_cnt;
    if (c > 0u) {
        if (tid == 0) s_base = atomicAdd(&g_cnt, c);
        __syncthreads();
        unsigned gb = s_base;
        for (unsigned j = tid; j < c; j += bs) g_keys[gb + j] = stage[j];
    }
    __syncthreads();
    for (int i = tid; i < 4096; i += bs) {
        unsigned hv = hist[i];
        if (hv) atomicAdd(&g_hist1[i], hv);
    }
}

// ---------------------------------------------------------------------------
// Pass B: refine bits 19:8 among keys matching p1. Reads compacted keys only.
__global__ void passB_kernel() {
    __shared__ unsigned hist[4096];
    const int tid = threadIdx.x, bs = blockDim.x;
    for (int i = tid; i < 4096; i += bs) hist[i] = 0u;
    __syncthreads();

    const unsigned cnt = g_cnt;
    const unsigned p1  = g_p1;
    const uint4* k4 = (const uint4*)g_keys;
    const unsigned m4 = cnt >> 2;
    const unsigned S = gridDim.x * bs;
    unsigned i = blockIdx.x * bs + tid;

#define PROC(u) do {                                              \
        if (((u).x >> 20) == p1) atomicAdd(&hist[((u).x >> 8) & 0xFFFu], 1u); \
        if (((u).y >> 20) == p1) atomicAdd(&hist[((u).y >> 8) & 0xFFFu], 1u); \
        if (((u).z >> 20) == p1) atomicAdd(&hist[((u).z >> 8) & 0xFFFu], 1u); \
        if (((u).w >> 20) == p1) atomicAdd(&hist[((u).w >> 8) & 0xFFFu], 1u); } while (0)
    for (; i + 3u * S < m4; i += 4u * S) {
        uint4 a = k4[i], b = k4[i + S], c = k4[i + 2u * S], d = k4[i + 3u * S];
        PROC(a); PROC(b); PROC(c); PROC(d);
    }
    for (; i < m4; i += S) { uint4 a = k4[i]; PROC(a); }
#undef PROC
    if (blockIdx.x == 0) {
        for (unsigned j = (m4 << 2) + tid; j < cnt; j += bs) {
            unsigned u = g_keys[j];
            if ((u >> 20) == p1) atomicAdd(&hist[(u >> 8) & 0xFFFu], 1u);
        }
    }
    __syncthreads();
    for (int i2 = tid; i2 < 4096; i2 += bs) {
        unsigned hv = hist[i2];
        if (hv) atomicAdd(&g_hist2[i2], hv);
    }
}

// ---------------------------------------------------------------------------
// Pass C: refine bits 7:0 among keys matching 24-bit prefix p2.
__global__ void passC_kernel() {
    __shared__ unsigned hist[256];
    const int tid = threadIdx.x, bs = blockDim.x;
    for (int i = tid; i < 256; i += bs) hist[i] = 0u;
    __syncthreads();

    const unsigned cnt = g_cnt;
    const unsigned p2  = g_p2;
    const uint4* k4 = (const uint4*)g_keys;
    const unsigned m4 = cnt >> 2;
    const unsigned S = gridDim.x * bs;
    unsigned i = blockIdx.x * bs + tid;

#define PROC(u) do {                                              \
        if (((u).x >> 8) == p2) atomicAdd(&hist[(u).x & 0xFFu], 1u); \
        if (((u).y >> 8) == p2) atomicAdd(&hist[(u).y & 0xFFu], 1u); \
        if (((u).z >> 8) == p2) atomicAdd(&hist[(u).z & 0xFFu], 1u); \
        if (((u).w >> 8) == p2) atomicAdd(&hist[(u).w & 0xFFu], 1u); } while (0)
    for (; i + 3u * S < m4; i += 4u * S) {
        uint4 a = k4[i], b = k4[i + S], c = k4[i + 2u * S], d = k4[i + 3u * S];
        PROC(a); PROC(b); PROC(c); PROC(d);
    }
    for (; i < m4; i += S) { uint4 a = k4[i]; PROC(a); }
#undef PROC
    if (blockIdx.x == 0) {
        for (unsigned j = (m4 << 2) + tid; j < cnt; j += bs) {
            unsigned u = g_keys[j];
            if ((u >> 8) == p2) atomicAdd(&hist[u & 0xFFu], 1u);
        }
    }
    __syncthreads();
    for (int i2 = tid; i2 < 256; i2 += bs) {
        unsigned hv = hist[i2];
        if (hv) atomicAdd(&g_hist3[i2], hv);
    }
}

// ---------------------------------------------------------------------------
// Generic select: suffix-scan histogram, locate rank-k bin from the top.
// 1024 threads, each owns 4 consecutive bins (bins beyond nbins read as 0).
__global__ void select_kernel(int stage) {
    __shared__ unsigned smW[32];
    __shared__ unsigned smE[32];
    __shared__ unsigned sTotal;

    const int tid  = threadIdx.x;
    const int lane = tid & 31;
    const int wid  = tid >> 5;

    const unsigned* hist = (stage == 0) ? g_hist1 : (stage == 1) ? g_hist2 : g_hist3;
    const int nbins      = (stage == 2) ? 256 : 4096;

    unsigned h0 = 0, h1 = 0, h2 = 0, h3 = 0;
    int b0 = tid * 4;
    if (b0 + 0 < nbins) h0 = hist[b0 + 0];
    if (b0 + 1 < nbins) h1 = hist[b0 + 1];
    if (b0 + 2 < nbins) h2 = hist[b0 + 2];
    if (b0 + 3 < nbins) h3 = hist[b0 + 3];
    unsigned s = h0 + h1 + h2 + h3;

    // warp inclusive suffix scan
    unsigned v = s;
#pragma unroll
    for (int d = 1; d < 32; d <<= 1) {
        unsigned u = __shfl_down_sync(0xffffffffu, v, d);
        if (lane + d < 32) v += u;
    }
    if (lane == 0) smW[wid] = v;
    __syncthreads();
    if (wid == 0) {
        unsigned wv = smW[lane];
        unsigned wi = wv;
#pragma unroll
        for (int d = 1; d < 32; d <<= 1) {
            unsigned u = __shfl_down_sync(0xffffffffu, wi, d);
            if (lane + d < 32) wi += u;
        }
        smE[lane] = wi - wv;          // sum of warps strictly above
        if (lane == 0) sTotal = wi;   // grand total
    }
    __syncthreads();
    unsigned sfx = v + smE[wid];      // suffix starting at this thread's first bin

    // defaults, mode flags, zero next histogram
    if (tid == 0) {
        if (stage == 0) {
            unsigned kk = g_k0;
            g_mode = (kk == 0u) ? 1 : (kk > sTotal ? 2 : 0);
            g_p1 = 0u; g_k1 = 0u;
        } else if (stage == 1) {
            g_p2 = 0u; g_k2 = 0u;
        } else {
            int m = g_mode;
            if (m == 1) g_thr = __int_as_float(0x7f800000);  // +inf: keep all
            else if (m == 2) g_thr = 0.0f;                   // drop all negs
        }
    }
    if (stage == 0) { for (int i = tid; i < 4096; i += blockDim.x) g_hist2[i] = 0u; }
    if (stage == 1) { if (tid < 256) g_hist3[tid] = 0u; }
    __syncthreads();

    int mode = g_mode;  // stage 0: just written; later stages: from prior kernel
    if (stage == 0) mode = (g_k0 == 0u) ? 1 : (g_k0 > sTotal ? 2 : 0);
    unsigned kk = (stage == 0) ? g_k0 : (stage == 1) ? g_k1 : g_k2;
    if (mode != 0 || kk == 0u) return;

    unsigned run = sfx;
    unsigned hh[4] = {h0, h1, h2, h3};
#pragma unroll
    for (int j = 0; j < 4; j++) {
        int bin = b0 + j;
        if (bin < nbins) {
            unsigned next = run - hh[j];
            if (run >= kk && next < kk) {
                if (stage == 0)      { g_p1 = (unsigned)bin;                g_k1 = kk - next; }
                else if (stage == 1) { g_p2 = (g_p1 << 12) | (unsigned)bin; g_k2 = kk - next; }
                else {
                    unsigned key = (g_p2 << 8) | (unsigned)bin;
                    g_thr = neg_loss_f(key2f(key));
                }
            }
            run = next;
        }
    }
}

// ---------------------------------------------------------------------------
__device__ __forceinline__ float elem_loss(float x, float t, float thr) {
    float ax  = fabsf(x);
    float lse = log1pf(expf(-ax));
    float pl  = fmaxf(-x, 0.0f) + lse;   // positive-branch loss
    float nl  = fmaxf( x, 0.0f) + lse;   // negative-branch loss (softplus(x))
    float r = 0.0f;
    if (t > 0.0f) r = pl;
    else if (t < 0.0f) r = (nl < thr) ? nl : 0.0f;
    return r;
}

__global__ void finalize_kernel(const float* __restrict__ in,
                                const float* __restrict__ tg,
                                float* __restrict__ out, int n) {
    const float thr = g_thr;
    const float4* in4 = (const float4*)in;
    const float4* tg4 = (const float4*)tg;
    float4* o4 = (float4*)out;
    const int n4 = n >> 2;
    const int S = gridDim.x * blockDim.x;
    int i = blockIdx.x * blockDim.x + threadIdx.x;

    for (; i + S < n4; i += 2 * S) {
        float4 x0 = in4[i], t0 = tg4[i];
        float4 x1 = in4[i + S], t1 = tg4[i + S];
        float4 o0, o1;
        o0.x = elem_loss(x0.x, t0.x, thr); o0.y = elem_loss(x0.y, t0.y, thr);
        o0.z = elem_loss(x0.z, t0.z, thr); o0.w = elem_loss(x0.w, t0.w, thr);
        o1.x = elem_loss(x1.x, t1.x, thr); o1.y = elem_loss(x1.y, t1.y, thr);
        o1.z = elem_loss(x1.z, t1.z, thr); o1.w = elem_loss(x1.w, t1.w, thr);
        o4[i] = o0;
        o4[i + S] = o1;
    }
    for (; i < n4; i += S) {
        float4 x0 = in4[i], t0 = tg4[i];
        float4 o0;
        o0.x = elem_loss(x0.x, t0.x, thr); o0.y = elem_loss(x0.y, t0.y, thr);
        o0.z = elem_loss(x0.z, t0.z, thr); o0.w = elem_loss(x0.w, t0.w, thr);
        o4[i] = o0;
    }
    if (blockIdx.x == 0) {
        for (int j = (n4 << 2) + threadIdx.x; j < n; j += blockDim.x)
            out[j] = elem_loss(in[j], tg[j], thr);
    }
}

// ---------------------------------------------------------------------------
extern "C" void kernel_launch(void* const* d_in, const int* in_sizes, int n_in,
                              void* d_out, int out_size) {
    const float* inp  = (const float*)d_in[0];
    const float* tgt  = (const float*)d_in[1];
    const int*   kptr = (const int*)d_in[2];
    float* out = (float*)d_out;
    const int n = in_sizes[0];

    init_kernel<<<1, 1024>>>(kptr);
    passA_kernel<<<1184, 256>>>(inp, tgt, n);
    select_kernel<<<1, 1024>>>(0);
    passB_kernel<<<296, 256>>>();
    select_kernel<<<1, 1024>>>(1);
    passC_kernel<<<296, 256>>>();
    select_kernel<<<1, 1024>>>(2);
    finalize_kernel<<<1184, 256>>>(out ? inp : inp, tgt, out, n);
}